// round 1
// baseline (speedup 1.0000x reference)
#include <cuda_runtime.h>
#include <math.h>

// Per-segment accumulators (scratch). B = 2048 in this problem; cap at 4096.
#define MAXB 4096
__device__ float g_seg_bce[MAXB];
__device__ float g_seg_cnt[MAXB];

__device__ __forceinline__ float bce_elem(float p, float t) {
    // matches torch BCELoss / jax reference: logs clamped at -100
    float lp  = fmaxf(logf(p),     -100.0f);   // logf(0) = -inf -> -100
    float lq  = fmaxf(log1pf(-p),  -100.0f);
    return -(t * lp + (1.0f - t) * lq);
}

__global__ void zero_kernel(int B) {
    int i = blockIdx.x * blockDim.x + threadIdx.x;
    if (i < B) { g_seg_bce[i] = 0.0f; g_seg_cnt[i] = 0.0f; }
}

__global__ void node_kernel(const float* __restrict__ pred,
                            const float* __restrict__ tgt,
                            const int*   __restrict__ batch,
                            const int*   __restrict__ mask,
                            int n) {
    const unsigned FULL = 0xffffffffu;
    int i = blockIdx.x * blockDim.x + threadIdx.x;
    bool valid = (i < n);
    unsigned act = __ballot_sync(FULL, valid);
    if (!valid) return;

    float m = (float)mask[i];
    float p = pred[i] * m;          // masked prediction (masked-out => p=0 => bce=100*t)
    float t = tgt[i];
    float b = bce_elem(p, t);
    int seg = batch[i];

    if (act == FULL) {
        // batch is sorted: overwhelmingly the whole warp is one segment.
        int lo = __shfl_sync(FULL, seg, 0);
        int hi = __shfl_sync(FULL, seg, 31);
        if (lo == hi) {
            #pragma unroll
            for (int o = 16; o; o >>= 1) {
                b += __shfl_down_sync(FULL, b, o);
                m += __shfl_down_sync(FULL, m, o);
            }
            if ((threadIdx.x & 31) == 0) {
                atomicAdd(&g_seg_bce[seg], b);
                atomicAdd(&g_seg_cnt[seg], m);
            }
            return;
        }
    }
    // boundary warps (~B of them total) fall back to per-lane atomics
    atomicAdd(&g_seg_bce[seg], b);
    atomicAdd(&g_seg_cnt[seg], m);
}

__global__ void finalize_kernel(const float* __restrict__ sat_p,
                                const float* __restrict__ sat_t,
                                float* __restrict__ out,
                                int B, float l1) {
    __shared__ float sh[32];
    float acc = 0.0f;   // sum of per-graph normalized bce
    float sat = 0.0f;   // sum of saturation bce
    for (int i = threadIdx.x; i < B; i += blockDim.x) {
        float c  = g_seg_cnt[i];
        float sb = g_seg_bce[i];
        acc += (c > 0.0f) ? (sb / fmaxf(c, 1.0f)) : 0.0f;
        sat += bce_elem(sat_p[i], sat_t[i]);
    }
    float v = acc + sat * (l1 / (float)B);
    // block reduce
    const unsigned FULL = 0xffffffffu;
    #pragma unroll
    for (int o = 16; o; o >>= 1) v += __shfl_down_sync(FULL, v, o);
    int lane = threadIdx.x & 31, wid = threadIdx.x >> 5;
    if (lane == 0) sh[wid] = v;
    __syncthreads();
    if (wid == 0) {
        int nw = (blockDim.x + 31) >> 5;
        v = (lane < nw) ? sh[lane] : 0.0f;
        #pragma unroll
        for (int o = 16; o; o >>= 1) v += __shfl_down_sync(FULL, v, o);
        if (lane == 0) out[0] = v;
    }
}

extern "C" void kernel_launch(void* const* d_in, const int* in_sizes, int n_in,
                              void* d_out, int out_size) {
    const float* y_mus_pred = (const float*)d_in[0];
    const float* y_mus      = (const float*)d_in[1];
    const float* y_sat_pred = (const float*)d_in[2];
    const float* y_sat      = (const float*)d_in[3];
    const int*   batch      = (const int*)  d_in[4];
    const int*   mask       = (const int*)  d_in[5];
    int N = in_sizes[0];
    int B = in_sizes[2];
    float L1 = 1.0f / 50.0f;

    zero_kernel<<<(B + 255) / 256, 256>>>(B);
    node_kernel<<<(N + 255) / 256, 256>>>(y_mus_pred, y_mus, batch, mask, N);
    finalize_kernel<<<1, 1024>>>(y_sat_pred, y_sat, (float*)d_out, B, L1);
}

// round 2
// speedup vs baseline: 2.6516x; 2.6516x over previous
#include <cuda_runtime.h>
#include <math.h>

#define MAXB 4096
__device__ float g_seg_bce[MAXB];   // zero-initialized at module load; finalize re-zeroes
__device__ float g_seg_cnt[MAXB];

__device__ __forceinline__ float bce_fast(float p, float t) {
    // __logf: MUFU.LG2 * ln2. __logf(0) = -inf -> clamped to -100.
    float lp = fmaxf(__logf(p),        -100.0f);
    float lq = fmaxf(__logf(1.0f - p), -100.0f);
    return -(t * lp + (1.0f - t) * lq);
}

__global__ void __launch_bounds__(256) node_kernel(
        const float4* __restrict__ pred4,
        const float4* __restrict__ tgt4,
        const int4*   __restrict__ batch4,
        const int4*   __restrict__ mask4,
        int n4)        // number of float4 groups (N/4)
{
    const unsigned FULL = 0xffffffffu;
    int i = blockIdx.x * blockDim.x + threadIdx.x;
    if (i >= n4) return;

    float4 p4 = pred4[i];
    float4 t4 = tgt4[i];
    int4   s4 = batch4[i];
    int4   k4 = mask4[i];

    float m0 = (float)k4.x, m1 = (float)k4.y, m2 = (float)k4.z, m3 = (float)k4.w;
    float b0 = bce_fast(p4.x * m0, t4.x);
    float b1 = bce_fast(p4.y * m1, t4.y);
    float b2 = bce_fast(p4.z * m2, t4.z);
    float b3 = bce_fast(p4.w * m3, t4.w);

    // segment uniform across warp? (batch sorted; segments ~3900 long)
    int seg_lo = s4.x, seg_hi = s4.w;
    unsigned act = __ballot_sync(FULL, 1);
    int wlo = __shfl_sync(FULL, seg_lo, 0);
    int whi = __shfl_sync(FULL, seg_hi, 31);

    if (act == FULL && wlo == whi) {
        float b = (b0 + b1) + (b2 + b3);
        float m = (m0 + m1) + (m2 + m3);
        #pragma unroll
        for (int o = 16; o; o >>= 1) {
            b += __shfl_down_sync(FULL, b, o);
            m += __shfl_down_sync(FULL, m, o);
        }
        if ((threadIdx.x & 31) == 0) {
            atomicAdd(&g_seg_bce[wlo], b);
            atomicAdd(&g_seg_cnt[wlo], m);
        }
        return;
    }

    // boundary warp: per-thread aggregation when the 4 elems share a segment
    if (seg_lo == seg_hi) {
        atomicAdd(&g_seg_bce[seg_lo], (b0 + b1) + (b2 + b3));
        atomicAdd(&g_seg_cnt[seg_lo], (m0 + m1) + (m2 + m3));
    } else {
        atomicAdd(&g_seg_bce[s4.x], b0); atomicAdd(&g_seg_cnt[s4.x], m0);
        atomicAdd(&g_seg_bce[s4.y], b1); atomicAdd(&g_seg_cnt[s4.y], m1);
        atomicAdd(&g_seg_bce[s4.z], b2); atomicAdd(&g_seg_cnt[s4.z], m2);
        atomicAdd(&g_seg_bce[s4.w], b3); atomicAdd(&g_seg_cnt[s4.w], m3);
    }
}

// scalar tail (N not divisible by 4)
__global__ void tail_kernel(const float* __restrict__ pred,
                            const float* __restrict__ tgt,
                            const int*   __restrict__ batch,
                            const int*   __restrict__ mask,
                            int start, int n)
{
    int i = start + blockIdx.x * blockDim.x + threadIdx.x;
    if (i >= n) return;
    float m = (float)mask[i];
    float b = bce_fast(pred[i] * m, tgt[i]);
    atomicAdd(&g_seg_bce[batch[i]], b);
    atomicAdd(&g_seg_cnt[batch[i]], m);
}

__global__ void finalize_kernel(const float* __restrict__ sat_p,
                                const float* __restrict__ sat_t,
                                float* __restrict__ out,
                                int B, float l1)
{
    __shared__ float sh[32];
    const unsigned FULL = 0xffffffffu;
    float acc = 0.0f, sat = 0.0f;
    for (int i = threadIdx.x; i < B; i += blockDim.x) {
        float c  = g_seg_cnt[i];
        float sb = g_seg_bce[i];
        acc += (c > 0.0f) ? (sb / fmaxf(c, 1.0f)) : 0.0f;
        sat += bce_fast(sat_p[i], sat_t[i]);
        // re-zero for the next graph replay (deterministic: globals start zeroed)
        g_seg_cnt[i] = 0.0f;
        g_seg_bce[i] = 0.0f;
    }
    float v = acc + sat * (l1 / (float)B);
    #pragma unroll
    for (int o = 16; o; o >>= 1) v += __shfl_down_sync(FULL, v, o);
    int lane = threadIdx.x & 31, wid = threadIdx.x >> 5;
    if (lane == 0) sh[wid] = v;
    __syncthreads();
    if (wid == 0) {
        int nw = (blockDim.x + 31) >> 5;
        v = (lane < nw) ? sh[lane] : 0.0f;
        #pragma unroll
        for (int o = 16; o; o >>= 1) v += __shfl_down_sync(FULL, v, o);
        if (lane == 0) out[0] = v;
    }
}

extern "C" void kernel_launch(void* const* d_in, const int* in_sizes, int n_in,
                              void* d_out, int out_size) {
    const float* y_mus_pred = (const float*)d_in[0];
    const float* y_mus      = (const float*)d_in[1];
    const float* y_sat_pred = (const float*)d_in[2];
    const float* y_sat      = (const float*)d_in[3];
    const int*   batch      = (const int*)  d_in[4];
    const int*   mask       = (const int*)  d_in[5];
    int N = in_sizes[0];
    int B = in_sizes[2];
    float L1 = 1.0f / 50.0f;

    int n4 = N >> 2;                 // vectorized groups
    if (n4 > 0) {
        int blocks = (n4 + 255) / 256;
        node_kernel<<<blocks, 256>>>((const float4*)y_mus_pred,
                                     (const float4*)y_mus,
                                     (const int4*)batch,
                                     (const int4*)mask, n4);
    }
    int tail_start = n4 << 2;
    if (tail_start < N) {
        tail_kernel<<<1, 256>>>(y_mus_pred, y_mus, batch, mask, tail_start, N);
    }
    finalize_kernel<<<1, 1024>>>(y_sat_pred, y_sat, (float*)d_out, B, L1);
}